// round 10
// baseline (speedup 1.0000x reference)
#include <cuda_runtime.h>
#include <cuda_bf16.h>

// ParametricInterpolation, round 7.
//
// PROTECTED NUMERICS (R6 pass, rel_err 7.7e-8 — do not alter):
//   p_k  = rn( pb[k] * rn(1/scaler_k) )   (XLA divide-by-constant rewrite)
//   t2   = rn(t*t); t3 = rn(t2*t); t4 = rn(t2*t2)
//   cv   = fma-ascending: fmaf(p0,t4,0) -> fmaf(p1,t3,.) -> fmaf(p2,t2,.)
//          -> fmaf(p3,t,.) -> +p4
//   ci   = rintf(cv)  (half-to-even);  d = cv - ci  (exact)
//   gather: constant weights {e^-16, e^-1, 1, e^-1, e^-16}, ascending-j
//           partial sums, fmaf accumulate, __fadd_rn weight sums,
//           __fdiv_rn normalize.
//
// Perf change vs R6: the kernel was latency-bound on two SERIALIZED DRAM
// round-trips (params -> poly -> data-dependent gather from x). Now the
// 8KB x-row is staged into shared memory with coalesced float4 loads issued
// at kernel entry, overlapping the params-load + polynomial chain; the
// gather becomes 6 LDS hits after one barrier.

#ifndef SIG_LEN
#define SIG_LEN 2048
#endif

__global__ __launch_bounds__(256, 1)
void ParametricInterpolation_kernel(
    const float* __restrict__ x,       // [B, N]
    const float* __restrict__ params,  // [B, 5]
    float* __restrict__ out,           // [B, N]
    float* __restrict__ curve,         // [B, N] or nullptr
    int B)
{
    const int N = SIG_LEN;
    __shared__ float sx[SIG_LEN];      // one full x row (8 KB)

    int gid = blockIdx.x * blockDim.x + threadIdx.x;
    int b = gid >> 11;                 // 8 blocks per batch row
    int i = gid & (N - 1);

    // ---- Phase A: issue the coalesced row staging FIRST (independent of
    // params), so its DRAM latency overlaps the params->poly chain. ----
    {
        const float4* xr4 = reinterpret_cast<const float4*>(x + b * N);
        float4* s4 = reinterpret_cast<float4*>(sx);
        int tix = threadIdx.x;
        float4 v0 = __ldg(xr4 + tix);        // 256 threads x 2 float4 = 2048 f
        float4 v1 = __ldg(xr4 + tix + 256);
        s4[tix]       = v0;
        s4[tix + 256] = v1;
    }

    // ---- Phase B (overlapped): params load + rint-critical polynomial. ----
    const float r0 = __fdiv_rn(1.0f, 1e11f);   // constant-folded rn(1/c)
    const float r1 = __fdiv_rn(1.0f, 1e7f);
    const float r2 = __fdiv_rn(1.0f, 1e3f);

    const float* pb = params + b * 5;
    float p0 = __fmul_rn(__ldg(pb + 0), r0);
    float p1 = __fmul_rn(__ldg(pb + 1), r1);
    float p2 = __fmul_rn(__ldg(pb + 2), r2);
    float p3 = __ldg(pb + 3);
    float p4 = __ldg(pb + 4);

    float t  = (float)i;
    float t2 = __fmul_rn(t, t);
    float t3 = __fmul_rn(t2, t);
    float t4 = __fmul_rn(t2, t2);

    float cv = fmaf(p0, t4, 0.0f);
    cv = fmaf(p1, t3, cv);
    cv = fmaf(p2, t2, cv);
    cv = fmaf(p3, t,  cv);
    cv = __fadd_rn(cv, p4);

    float ci = rintf(cv);
    float d  = __fadd_rn(cv, -ci);

    float raw_pos = __fadd_rn(t, -ci);         // exact integer
    float np_f = fminf(fmaxf(raw_pos, 1.0f), 2047.0f);
    int m = (int)np_f;

    __syncthreads();   // row staged

    // ---- Phase C: constant-weight gather from shared memory.
    // Ascending-j order, identical f32 partial sums to R6/reference. ----
    const float W1 = 0.36787944117144233f;     // f32(exp(-1))
    const float W2 = 1.1253517471925912e-07f;  // f32(exp(-16))

    float s1 = 0.0f, w1s = 0.0f, s2 = 0.0f, w2s = 0.0f;

    #pragma unroll
    for (int o = -3; o <= 2; o++) {
        int j = m + o;
        if (j < 0 || j >= N) continue;
        float xv = sx[j];
        float wk1 = (o == 0) ? 1.0f
                  : (o == -1 || o == 1) ? W1
                  : (o == -2 || o == 2) ? W2 : 0.0f;
        int o2 = o + 1;
        float wk2 = (o2 == 0) ? 1.0f
                  : (o2 == -1 || o2 == 1) ? W1
                  : (o2 == -2 || o2 == 2) ? W2 : 0.0f;
        s1  = fmaf(xv, wk1, s1);
        w1s = __fadd_rn(w1s, wk1);
        s2  = fmaf(xv, wk2, s2);
        w2s = __fadd_rn(w2s, wk2);
    }

    float a1 = __fdiv_rn(s1, w1s);
    float a2 = __fdiv_rn(s2, w2s);

    float one_md = __fadd_rn(1.0f, -d);
    float o_val = __fadd_rn(__fmul_rn(a1, one_md), __fmul_rn(a2, d));

    out[gid] = o_val;
    if (curve) curve[gid] = cv;
}

extern "C" void kernel_launch(void* const* d_in, const int* in_sizes, int n_in,
                              void* d_out, int out_size)
{
    const float* x      = (const float*)d_in[0];   // [B, 2048] f32
    const float* params = (const float*)d_in[1];   // [B, 5]    f32
    float* out = (float*)d_out;

    int B = in_sizes[1] / 5;           // 16
    int total = B * SIG_LEN;           // 32768

    float* curve = (out_size >= 2 * total) ? (out + total) : nullptr;

    int threads = 256;
    int blocks = (total + threads - 1) / threads;  // 128
    ParametricInterpolation_kernel<<<blocks, threads>>>(x, params, out, curve, B);
}